// round 2
// baseline (speedup 1.0000x reference)
#include <cuda_runtime.h>
#include <math.h>

#define BB   4
#define LL   1024
#define HIDD 768
#define HH   12
#define DD   64
#define BH   (BB*HH)

// ---- scratch (device globals; no allocation allowed) ----
__device__ float g_q[BH * LL * DD];          // [bh, l, d]
__device__ float g_k[BH * LL * DD];
__device__ float g_v[BH * LL * DD];
__device__ float g_scores[(size_t)BH * LL * LL];  // [bh, l, r]  (201 MB)

// ---------------- packed f32x2 helpers (sm_103a FFMA2 path) ----------------
typedef unsigned long long u64;

__device__ __forceinline__ u64 pk2(float lo, float hi) {
    u64 d;
    asm("mov.b64 %0, {%1, %2};" : "=l"(d) : "f"(lo), "f"(hi));
    return d;
}
__device__ __forceinline__ void upk2(u64 v, float& lo, float& hi) {
    asm("mov.b64 {%0, %1}, %2;" : "=f"(lo), "=f"(hi) : "l"(v));
}
__device__ __forceinline__ u64 fma2(u64 a, u64 b, u64 c) {
    u64 d;
    asm("fma.rn.f32x2 %0, %1, %2, %3;" : "=l"(d) : "l"(a), "l"(b), "l"(c));
    return d;
}
__device__ __forceinline__ u64 add2(u64 a, u64 b) {
    u64 d;
    asm("add.rn.f32x2 %0, %1, %2;" : "=l"(d) : "l"(a), "l"(b));
    return d;
}

// ============================================================================
// K1: QKV projection.  Y = X @ W^T + b, scattered into [B,H,L,D].
// 128x128x8 tile, 256 threads, 8x8 microtile computed as 8x(4 f32x2 pairs).
// ============================================================================
__global__ __launch_bounds__(256) void qkv_kernel(
    const float* __restrict__ X,
    const float* __restrict__ W,
    const float* __restrict__ bias,
    int which)
{
    __shared__ float As[8][132];   // [kk][m]
    __shared__ float Bs[8][132];   // [kk][n]

    const int tid = threadIdx.x;
    const int m0 = blockIdx.x * 128;
    const int n0 = blockIdx.y * 128;
    const int tx = tid & 15;       // n-direction
    const int ty = tid >> 4;       // m-direction

    u64 accp[8][4];
#pragma unroll
    for (int i = 0; i < 8; i++)
#pragma unroll
        for (int j = 0; j < 4; j++) accp[i][j] = 0ull;

    const int lrow = tid >> 1;
    const int lc   = (tid & 1) * 4;
    const float* Xp = X + (size_t)(m0 + lrow) * HIDD + lc;
    const float* Wp = W + (size_t)(n0 + lrow) * HIDD + lc;

    for (int k0 = 0; k0 < HIDD; k0 += 8) {
        float4 av = *(const float4*)(Xp + k0);
        float4 bv = *(const float4*)(Wp + k0);
        __syncthreads();
        As[lc + 0][lrow] = av.x; As[lc + 1][lrow] = av.y;
        As[lc + 2][lrow] = av.z; As[lc + 3][lrow] = av.w;
        Bs[lc + 0][lrow] = bv.x; Bs[lc + 1][lrow] = bv.y;
        Bs[lc + 2][lrow] = bv.z; Bs[lc + 3][lrow] = bv.w;
        __syncthreads();
#pragma unroll
        for (int kk = 0; kk < 8; kk++) {
            float4 a0 = *(const float4*)&As[kk][ty * 4];
            float4 a1 = *(const float4*)&As[kk][64 + ty * 4];
            float4 b0 = *(const float4*)&Bs[kk][tx * 4];
            float4 b1 = *(const float4*)&Bs[kk][64 + tx * 4];
            u64 bu[4] = { pk2(b0.x, b0.y), pk2(b0.z, b0.w),
                          pk2(b1.x, b1.y), pk2(b1.z, b1.w) };
            float ar[8] = { a0.x, a0.y, a0.z, a0.w, a1.x, a1.y, a1.z, a1.w };
#pragma unroll
            for (int i = 0; i < 8; i++) {
                u64 au = pk2(ar[i], ar[i]);
#pragma unroll
                for (int j = 0; j < 4; j++)
                    accp[i][j] = fma2(au, bu[j], accp[i][j]);
            }
        }
    }

    float* out = (which == 0) ? g_q : (which == 1) ? g_k : g_v;
#pragma unroll
    for (int i = 0; i < 8; i++) {
        const int m = m0 + ((i < 4) ? (ty * 4 + i) : (64 + ty * 4 + (i - 4)));
        const int b_idx = m >> 10;
        const int l     = m & (LL - 1);
#pragma unroll
        for (int g = 0; g < 2; g++) {
            const int n_base = n0 + g * 64 + tx * 4;   // 4 consecutive n, same head
            const int h = n_base >> 6;
            const int d = n_base & 63;
            float c0, c1, c2, c3;
            upk2(accp[i][g * 2 + 0], c0, c1);
            upk2(accp[i][g * 2 + 1], c2, c3);
            float4 r;
            r.x = c0 + bias[n_base + 0];
            r.y = c1 + bias[n_base + 1];
            r.z = c2 + bias[n_base + 2];
            r.w = c3 + bias[n_base + 3];
            *(float4*)&out[(((size_t)b_idx * HH + h) * LL + l) * DD + d] = r;
        }
    }
}

// ============================================================================
// K2: scores[bh,l,r] = ( q.k + (q+k).S[l,r,:] ) * 0.125 + mask[b,r]
//     = ( q.(k+s) + k.s ) * 0.125 + mask   (packed f32x2, 4 indep. chains)
// 16x16 (l,r) tile; thread owns one (l,r), S[l,r,:] in 32 u64 regs, amortized
// over all 48 bh.  S read ONCE from HBM.  q/k tiles prefetched across compute.
// ============================================================================
__global__ __launch_bounds__(256, 2) void scores_kernel(
    const float* __restrict__ S,
    const float* __restrict__ mask)
{
    __shared__ __align__(16) float qs[16 * 68];   // [l][d] pad 4
    __shared__ __align__(16) float ks[16 * 68];   // [r][d] pad 4

    const int tid = threadIdx.x;
    const int l0 = blockIdx.y * 16;
    const int r0 = blockIdx.x * 16;
    const int li = tid >> 4;   // 0..15 (also the load row)
    const int ri = tid & 15;

    // this thread's S row -> 32 packed u64 regs
    u64 s2[32];
    {
        const float4* sp = (const float4*)(S + (((size_t)(l0 + li)) * LL + (r0 + ri)) * DD);
#pragma unroll
        for (int t = 0; t < 16; t++) {
            float4 v = sp[t];
            s2[2 * t]     = pk2(v.x, v.y);
            s2[2 * t + 1] = pk2(v.z, v.w);
        }
    }
    // mask values for this thread's r, all 4 batches
    float maskv[BB];
#pragma unroll
    for (int b = 0; b < BB; b++) maskv[b] = mask[b * LL + r0 + ri];

    const int row = li;            // load row = tid>>4
    const int c4  = ri;            // float4 column = tid&15
    const size_t qoff = ((size_t)(l0 + row)) * DD + c4 * 4;
    const size_t koff = ((size_t)(r0 + row)) * DD + c4 * 4;

    float4 qpre = *(const float4*)(g_q + qoff);
    float4 kpre = *(const float4*)(g_k + koff);

    float* srow_out = g_scores + ((size_t)(l0 + li)) * LL + (r0 + ri);

    int b_idx = 0, hcnt = 0;
    for (int bh = 0; bh < BH; bh++) {
        __syncthreads();
        *(float4*)&qs[row * 68 + c4 * 4] = qpre;
        *(float4*)&ks[row * 68 + c4 * 4] = kpre;
        __syncthreads();
        if (bh + 1 < BH) {
            qpre = *(const float4*)(g_q + (size_t)(bh + 1) * (LL * DD) + qoff);
            kpre = *(const float4*)(g_k + (size_t)(bh + 1) * (LL * DD) + koff);
        }

        u64 aA = 0ull, aB = 0ull, aC = 0ull, aD = 0ull;
#pragma unroll
        for (int d4 = 0; d4 < 16; d4++) {
            float4 q4 = *(const float4*)&qs[li * 68 + d4 * 4];
            float4 k4 = *(const float4*)&ks[ri * 68 + d4 * 4];
            u64 q01 = pk2(q4.x, q4.y), q23 = pk2(q4.z, q4.w);
            u64 k01 = pk2(k4.x, k4.y), k23 = pk2(k4.z, k4.w);
            u64 s01 = s2[2 * d4], s23 = s2[2 * d4 + 1];
            u64 t01 = add2(k01, s01);
            u64 t23 = add2(k23, s23);
            aA = fma2(q01, t01, aA);
            aB = fma2(k01, s01, aB);
            aC = fma2(q23, t23, aC);
            aD = fma2(k23, s23, aD);
        }
        float x0, x1, y0, y1, z0, z1, w0, w1;
        upk2(aA, x0, x1); upk2(aB, y0, y1);
        upk2(aC, z0, z1); upk2(aD, w0, w1);
        float total = ((x0 + y0) + (x1 + y1)) + ((z0 + w0) + (z1 + w1));

        srow_out[(size_t)bh * (LL * LL)] = total * 0.125f + maskv[b_idx];
        if (++hcnt == HH) { hcnt = 0; b_idx++; }
    }
}

// ============================================================================
// K3: row softmax over r, then ctx = P @ V  (f32x2 microtile).
// ============================================================================
__global__ __launch_bounds__(256) void softmax_pv_kernel(float* __restrict__ out)
{
    __shared__ __align__(16) float Vs[64 * 68];   // [r][d] pad 4
    __shared__ float Ps[64 * 68];                 // [l][k] pad 4
    __shared__ float rmax[64], rinv[64];

    const int tid  = threadIdx.x;
    const int bh   = blockIdx.y;
    const int l0   = blockIdx.x * 64;
    const int warp = tid >> 5;
    const int lane = tid & 31;

    const float* srow_base = g_scores + ((size_t)bh * LL + l0) * LL;

    // ---- phase 1: per-row max and sum(exp), float4 loads ----
    for (int rr = warp; rr < 64; rr += 8) {
        const float4* s4 = (const float4*)(srow_base + (size_t)rr * LL);
        float4 v[8];
#pragma unroll
        for (int j = 0; j < 8; j++) v[j] = s4[lane + 32 * j];
        float m = -1e30f;
#pragma unroll
        for (int j = 0; j < 8; j++) {
            m = fmaxf(m, fmaxf(fmaxf(v[j].x, v[j].y), fmaxf(v[j].z, v[j].w)));
        }
#pragma unroll
        for (int o = 16; o > 0; o >>= 1) m = fmaxf(m, __shfl_xor_sync(0xffffffffu, m, o));
        float s = 0.f;
#pragma unroll
        for (int j = 0; j < 8; j++) {
            s += __expf(v[j].x - m) + __expf(v[j].y - m)
               + __expf(v[j].z - m) + __expf(v[j].w - m);
        }
#pragma unroll
        for (int o = 16; o > 0; o >>= 1) s += __shfl_xor_sync(0xffffffffu, s, o);
        if (lane == 0) { rmax[rr] = m; rinv[rr] = 1.f / s; }
    }
    __syncthreads();

    // ---- phase 2: P @ V ----
    const int tx = tid & 15;   // d-direction (4 cols)
    const int ty = tid >> 4;   // l-direction (4 rows)
    u64 accp[4][2];
#pragma unroll
    for (int i = 0; i < 4; i++) { accp[i][0] = 0ull; accp[i][1] = 0ull; }

    for (int rc = 0; rc < LL; rc += 64) {
        __syncthreads();
        // V chunk
        {
            const float4* vp = (const float4*)(g_v + ((size_t)bh * LL + rc) * DD);
            for (int idx = tid; idx < 64 * 16; idx += 256) {
                const int r  = idx >> 4;
                const int cc = idx & 15;
                *(float4*)&Vs[r * 68 + cc * 4] = vp[r * 16 + cc];
            }
        }
        // P chunk (exp recompute): Ps[l][k]
        for (int idx = tid; idx < 64 * 64; idx += 256) {
            const int l = idx >> 6;
            const int k = idx & 63;
            const float sc = srow_base[(size_t)l * LL + rc + k];
            Ps[l * 68 + k] = __expf(sc - rmax[l]);
        }
        __syncthreads();

#pragma unroll 4
        for (int k = 0; k < 64; k++) {
            const float4 v4 = *(const float4*)&Vs[k * 68 + tx * 4];
            u64 v01 = pk2(v4.x, v4.y);
            u64 v23 = pk2(v4.z, v4.w);
#pragma unroll
            for (int i = 0; i < 4; i++) {
                const float p = Ps[(ty * 4 + i) * 68 + k];
                u64 pd = pk2(p, p);
                accp[i][0] = fma2(pd, v01, accp[i][0]);
                accp[i][1] = fma2(pd, v23, accp[i][1]);
            }
        }
    }

    // ---- write: out[b, l, h*64 + d] ----
    const int b_idx = bh / HH;
    const int h     = bh % HH;
#pragma unroll
    for (int i = 0; i < 4; i++) {
        const int lrow = ty * 4 + i;
        const float inv = rinv[lrow];
        const int l = l0 + lrow;
        float c0, c1, c2, c3;
        upk2(accp[i][0], c0, c1);
        upk2(accp[i][1], c2, c3);
        float4 r;
        r.x = c0 * inv; r.y = c1 * inv; r.z = c2 * inv; r.w = c3 * inv;
        *(float4*)&out[((size_t)(b_idx * LL + l)) * HIDD + h * DD + tx * 4] = r;
    }
}

// ============================================================================
// launch
// ============================================================================
extern "C" void kernel_launch(void* const* d_in, const int* in_sizes, int n_in,
                              void* d_out, int out_size)
{
    (void)in_sizes; (void)n_in; (void)out_size;
    const float* hidden = (const float*)d_in[0];
    const float* mask   = (const float*)d_in[1];
    const float* S      = (const float*)d_in[2];
    const float* Wq     = (const float*)d_in[3];
    const float* bq     = (const float*)d_in[4];
    const float* Wk     = (const float*)d_in[5];
    const float* bk     = (const float*)d_in[6];
    const float* Wv     = (const float*)d_in[7];
    const float* bv     = (const float*)d_in[8];
    float* out = (float*)d_out;

    dim3 g1(32, 6);
    qkv_kernel<<<g1, 256>>>(hidden, Wq, bq, 0);
    qkv_kernel<<<g1, 256>>>(hidden, Wk, bk, 1);
    qkv_kernel<<<g1, 256>>>(hidden, Wv, bv, 2);

    dim3 g2(LL / 16, LL / 16);
    scores_kernel<<<g2, 256>>>(S, mask);

    dim3 g3(LL / 64, BH);
    softmax_pv_kernel<<<g3, 256>>>(out);
}

// round 3
// speedup vs baseline: 3.1116x; 3.1116x over previous
#include <cuda_runtime.h>
#include <math.h>

#define BB   4
#define LL   1024
#define HIDD 768
#define HH   12
#define DD   64
#define BH   (BB*HH)

// ---- scratch (device globals; no allocation allowed) ----
__device__ float g_q[BH * LL * DD];                 // [bh, l, d]  (pre-scaled by 0.125)
__device__ float g_k[BH * LL * DD];                 // [bh, l, d]
__device__ float g_v[BH * LL * DD];                 // [bh, l, d]
__device__ float g_scores[(size_t)BH * LL * LL];    // [bh, l, r]  = (qk + qS)/8 + mask
__device__ float g_scoresT[(size_t)BH * LL * LL];   // [bh, r, l]  = (kS)/8

// ---------------- tf32 mma helpers ----------------
__device__ __forceinline__ unsigned tf32cvt(float x) {
    unsigned u;
    asm("cvt.rna.tf32.f32 %0, %1;" : "=r"(u) : "f"(x));
    return u;
}
__device__ __forceinline__ void mma_tf32(float& c0, float& c1, float& c2, float& c3,
                                         unsigned a0, unsigned a1, unsigned a2, unsigned a3,
                                         unsigned b0, unsigned b1) {
    asm("mma.sync.aligned.m16n8k8.row.col.f32.tf32.tf32.f32 "
        "{%0,%1,%2,%3},{%4,%5,%6,%7},{%8,%9},{%0,%1,%2,%3};"
        : "+f"(c0), "+f"(c1), "+f"(c2), "+f"(c3)
        : "r"(a0), "r"(a1), "r"(a2), "r"(a3), "r"(b0), "r"(b1));
}

// ============================================================================
// K1: QKV projection, tf32 mma.  Y = X @ W^T + b, scattered into [BH, L, D].
// Block tile: M=64 x N=64, K-loop 768 in chunks of 64.  8 warps: 4 m-strips
// x 2 n-halves of 32.  q is stored pre-scaled by 0.125.
// ============================================================================
__global__ __launch_bounds__(256) void qkv_mma_kernel(
    const float* __restrict__ X,
    const float* __restrict__ W,
    const float* __restrict__ bias,
    int which)
{
    __shared__ unsigned Xs[64][68];   // [m][k]
    __shared__ unsigned Ws[64][68];   // [n][k]

    const int tid  = threadIdx.x;
    const int warp = tid >> 5;
    const int lane = tid & 31;
    const int m0 = blockIdx.x * 64;
    const int n0 = blockIdx.y * 64;
    const int mstrip = (warp & 3) * 16;
    const int nh     = (warp >> 2) * 32;

    float acc[4][4];
#pragma unroll
    for (int i = 0; i < 4; i++)
#pragma unroll
        for (int j = 0; j < 4; j++) acc[i][j] = 0.f;

    for (int k0 = 0; k0 < HIDD; k0 += 64) {
        __syncthreads();
#pragma unroll
        for (int i = 0; i < 4; i++) {
            const int idx = tid + i * 256;
            const int row = idx >> 4;
            const int c4  = idx & 15;
            float4 xv = *(const float4*)(X + (size_t)(m0 + row) * HIDD + k0 + c4 * 4);
            float4 wv = *(const float4*)(W + (size_t)(n0 + row) * HIDD + k0 + c4 * 4);
            Xs[row][c4 * 4 + 0] = tf32cvt(xv.x); Xs[row][c4 * 4 + 1] = tf32cvt(xv.y);
            Xs[row][c4 * 4 + 2] = tf32cvt(xv.z); Xs[row][c4 * 4 + 3] = tf32cvt(xv.w);
            Ws[row][c4 * 4 + 0] = tf32cvt(wv.x); Ws[row][c4 * 4 + 1] = tf32cvt(wv.y);
            Ws[row][c4 * 4 + 2] = tf32cvt(wv.z); Ws[row][c4 * 4 + 3] = tf32cvt(wv.w);
        }
        __syncthreads();
#pragma unroll
        for (int ks = 0; ks < 8; ks++) {
            const int kc = ks * 8 + (lane & 3);
            unsigned a0 = Xs[mstrip + (lane >> 2)][kc];
            unsigned a1 = Xs[mstrip + (lane >> 2) + 8][kc];
            unsigned a2 = Xs[mstrip + (lane >> 2)][kc + 4];
            unsigned a3 = Xs[mstrip + (lane >> 2) + 8][kc + 4];
#pragma unroll
            for (int nt = 0; nt < 4; nt++) {
                const int nb = nh + nt * 8;
                unsigned b0 = Ws[nb + (lane >> 2)][kc];
                unsigned b1 = Ws[nb + (lane >> 2)][kc + 4];
                mma_tf32(acc[nt][0], acc[nt][1], acc[nt][2], acc[nt][3],
                         a0, a1, a2, a3, b0, b1);
            }
        }
    }

    float* out = (which == 0) ? g_q : (which == 1) ? g_k : g_v;
    const float scale = (which == 0) ? 0.125f : 1.0f;
    const int row0 = m0 + mstrip + (lane >> 2);
#pragma unroll
    for (int nt = 0; nt < 4; nt++) {
        const int col = n0 + nh + nt * 8 + 2 * (lane & 3);
        const int h = col >> 6;
        const int d = col & 63;
#pragma unroll
        for (int half = 0; half < 2; half++) {
            const int row = row0 + half * 8;
            const int b_idx = row >> 10;
            const int l     = row & (LL - 1);
            float2 r;
            r.x = (acc[nt][2 * half + 0] + bias[col + 0]) * scale;
            r.y = (acc[nt][2 * half + 1] + bias[col + 1]) * scale;
            *(float2*)&out[(((size_t)b_idx * HH + h) * LL + l) * DD + d] = r;
        }
    }
}

// ============================================================================
// K2a: scores[bh,l,r] = q.k (q pre-scaled) + mask[b,r].   tf32 mma.
// Block tile: 64(l) x 64(r) per bh.  K = 64, single smem-resident chunk.
// ============================================================================
__global__ __launch_bounds__(256) void qk_mma_kernel(const float* __restrict__ mask)
{
    __shared__ unsigned Qs[64][68];   // [l][d]
    __shared__ unsigned Ks[64][68];   // [r][d]

    const int tid  = threadIdx.x;
    const int warp = tid >> 5;
    const int lane = tid & 31;
    const int r0 = blockIdx.x * 64;
    const int l0 = blockIdx.y * 64;
    const int bh = blockIdx.z;
    const int mstrip = (warp & 3) * 16;
    const int nh     = (warp >> 2) * 32;

#pragma unroll
    for (int i = 0; i < 4; i++) {
        const int idx = tid + i * 256;
        const int row = idx >> 4;
        const int c4  = idx & 15;
        float4 qv = *(const float4*)(g_q + ((size_t)bh * LL + l0 + row) * DD + c4 * 4);
        float4 kv = *(const float4*)(g_k + ((size_t)bh * LL + r0 + row) * DD + c4 * 4);
        Qs[row][c4 * 4 + 0] = tf32cvt(qv.x); Qs[row][c4 * 4 + 1] = tf32cvt(qv.y);
        Qs[row][c4 * 4 + 2] = tf32cvt(qv.z); Qs[row][c4 * 4 + 3] = tf32cvt(qv.w);
        Ks[row][c4 * 4 + 0] = tf32cvt(kv.x); Ks[row][c4 * 4 + 1] = tf32cvt(kv.y);
        Ks[row][c4 * 4 + 2] = tf32cvt(kv.z); Ks[row][c4 * 4 + 3] = tf32cvt(kv.w);
    }
    __syncthreads();

    float acc[4][4];
#pragma unroll
    for (int i = 0; i < 4; i++)
#pragma unroll
        for (int j = 0; j < 4; j++) acc[i][j] = 0.f;

#pragma unroll
    for (int ks = 0; ks < 8; ks++) {
        const int kc = ks * 8 + (lane & 3);
        unsigned a0 = Qs[mstrip + (lane >> 2)][kc];
        unsigned a1 = Qs[mstrip + (lane >> 2) + 8][kc];
        unsigned a2 = Qs[mstrip + (lane >> 2)][kc + 4];
        unsigned a3 = Qs[mstrip + (lane >> 2) + 8][kc + 4];
#pragma unroll
        for (int nt = 0; nt < 4; nt++) {
            const int nb = nh + nt * 8;
            unsigned b0 = Ks[nb + (lane >> 2)][kc];
            unsigned b1 = Ks[nb + (lane >> 2)][kc + 4];
            mma_tf32(acc[nt][0], acc[nt][1], acc[nt][2], acc[nt][3],
                     a0, a1, a2, a3, b0, b1);
        }
    }

    const int b_idx = bh / HH;
    const int row0 = l0 + mstrip + (lane >> 2);
#pragma unroll
    for (int nt = 0; nt < 4; nt++) {
        const int col = r0 + nh + nt * 8 + 2 * (lane & 3);
        const float m0v = mask[b_idx * LL + col];
        const float m1v = mask[b_idx * LL + col + 1];
#pragma unroll
        for (int half = 0; half < 2; half++) {
            const int row = row0 + half * 8;
            float2 r;
            r.x = acc[nt][2 * half + 0] + m0v;
            r.y = acc[nt][2 * half + 1] + m1v;
            *(float2*)&g_scores[((size_t)bh * LL + row) * LL + col] = r;
        }
    }
}

// ============================================================================
// K2b/K2c: structure-bias GEMMs.  For a fixed index f:
//  variant 0 (q-side, f=l): g_scores[bh, f, n]  += q[bh,f,:] . S[f,n,:]
//  variant 1 (k-side, f=r): g_scoresT[bh, f, n]  = 0.125 * k[bh,f,:] . S[n,f,:]
// M = 64 (48 real bh, 16 zero-pad), N = 64 chunk, K = 64.
// ============================================================================
__global__ __launch_bounds__(256) void bias_mma_kernel(
    const float* __restrict__ S, int variant)
{
    __shared__ unsigned As[64][68];   // [bh][d]
    __shared__ unsigned Ss[64][68];   // [n][d]

    const int tid  = threadIdx.x;
    const int warp = tid >> 5;
    const int lane = tid & 31;
    const int n0 = blockIdx.x * 64;
    const int f  = blockIdx.y;
    const int mstrip = (warp & 3) * 16;
    const int nh     = (warp >> 2) * 32;

    const float* Aop = (variant == 0) ? g_q : g_k;

#pragma unroll
    for (int i = 0; i < 4; i++) {
        const int idx = tid + i * 256;
        const int row = idx >> 4;
        const int c4  = idx & 15;
        if (row < BH) {
            float4 av = *(const float4*)(Aop + ((size_t)row * LL + f) * DD + c4 * 4);
            As[row][c4 * 4 + 0] = tf32cvt(av.x); As[row][c4 * 4 + 1] = tf32cvt(av.y);
            As[row][c4 * 4 + 2] = tf32cvt(av.z); As[row][c4 * 4 + 3] = tf32cvt(av.w);
        } else {
            As[row][c4 * 4 + 0] = 0u; As[row][c4 * 4 + 1] = 0u;
            As[row][c4 * 4 + 2] = 0u; As[row][c4 * 4 + 3] = 0u;
        }
        size_t soff = (variant == 0)
            ? (((size_t)f * LL + n0 + row) * DD + c4 * 4)
            : (((size_t)(n0 + row) * LL + f) * DD + c4 * 4);
        float4 sv = *(const float4*)(S + soff);
        Ss[row][c4 * 4 + 0] = tf32cvt(sv.x); Ss[row][c4 * 4 + 1] = tf32cvt(sv.y);
        Ss[row][c4 * 4 + 2] = tf32cvt(sv.z); Ss[row][c4 * 4 + 3] = tf32cvt(sv.w);
    }
    __syncthreads();

    float acc[4][4];
#pragma unroll
    for (int i = 0; i < 4; i++)
#pragma unroll
        for (int j = 0; j < 4; j++) acc[i][j] = 0.f;

#pragma unroll
    for (int ks = 0; ks < 8; ks++) {
        const int kc = ks * 8 + (lane & 3);
        unsigned a0 = As[mstrip + (lane >> 2)][kc];
        unsigned a1 = As[mstrip + (lane >> 2) + 8][kc];
        unsigned a2 = As[mstrip + (lane >> 2)][kc + 4];
        unsigned a3 = As[mstrip + (lane >> 2) + 8][kc + 4];
#pragma unroll
        for (int nt = 0; nt < 4; nt++) {
            const int nb = nh + nt * 8;
            unsigned b0 = Ss[nb + (lane >> 2)][kc];
            unsigned b1 = Ss[nb + (lane >> 2)][kc + 4];
            mma_tf32(acc[nt][0], acc[nt][1], acc[nt][2], acc[nt][3],
                     a0, a1, a2, a3, b0, b1);
        }
    }

    const int row0 = mstrip + (lane >> 2);   // bh index
#pragma unroll
    for (int nt = 0; nt < 4; nt++) {
        const int col = n0 + nh + nt * 8 + 2 * (lane & 3);
#pragma unroll
        for (int half = 0; half < 2; half++) {
            const int bh = row0 + half * 8;
            if (bh >= BH) continue;
            float* dst;
            if (variant == 0) {
                dst = &g_scores[((size_t)bh * LL + f) * LL + col];
                float2 old = *(float2*)dst;
                float2 r;
                r.x = old.x + acc[nt][2 * half + 0];
                r.y = old.y + acc[nt][2 * half + 1];
                *(float2*)dst = r;
            } else {
                dst = &g_scoresT[((size_t)bh * LL + f) * LL + col];
                float2 r;
                r.x = acc[nt][2 * half + 0] * 0.125f;
                r.y = acc[nt][2 * half + 1] * 0.125f;
                *(float2*)dst = r;
            }
        }
    }
}

// ============================================================================
// K3: single-pass online softmax + P@V.
// Block = (bh, 64 l-rows).  r-chunks of 32.  s = scores[l,r] + scoresT[r,l].
// ============================================================================
__global__ __launch_bounds__(256) void softmax_pv_kernel(float* __restrict__ out)
{
    __shared__ float As[64 * 33];               // [l][r] chunk -> reused as P
    __shared__ float Ts[32 * 65];               // [r][l] chunk (transposed bias)
    __shared__ __align__(16) float Vs[32 * 68]; // [r][d]
    __shared__ float m_state[64], sum_state[64], scalef[64];

    const int tid  = threadIdx.x;
    const int warp = tid >> 5;
    const int lane = tid & 31;
    const int bh   = blockIdx.y;
    const int l0   = blockIdx.x * 64;

    const int tx = tid & 15;   // d microtile
    const int ty = tid >> 4;   // l microtile
    float acc[4][4];
#pragma unroll
    for (int i = 0; i < 4; i++)
#pragma unroll
        for (int j = 0; j < 4; j++) acc[i][j] = 0.f;

    if (tid < 64) { m_state[tid] = -1e30f; sum_state[tid] = 0.f; }
    __syncthreads();

    for (int rc = 0; rc < LL; rc += 32) {
        // ---- loads ----
#pragma unroll
        for (int i = 0; i < 8; i++) {          // As: 64 x 32 scalar
            const int idx = tid + i * 256;
            const int row = idx >> 5;
            const int col = idx & 31;
            As[row * 33 + col] =
                g_scores[((size_t)bh * LL + l0 + row) * LL + rc + col];
        }
#pragma unroll
        for (int i = 0; i < 8; i++) {          // Ts: 32 x 64 scalar
            const int idx = tid + i * 256;
            const int row = idx >> 6;
            const int col = idx & 63;
            Ts[row * 65 + col] =
                g_scoresT[((size_t)bh * LL + rc + row) * LL + l0 + col];
        }
#pragma unroll
        for (int i = 0; i < 2; i++) {          // Vs: 32 x 64 float4
            const int idx = tid + i * 256;
            const int row = idx >> 4;
            const int c4  = idx & 15;
            *(float4*)&Vs[row * 68 + c4 * 4] =
                *(const float4*)(g_v + ((size_t)bh * LL + rc + row) * DD + c4 * 4);
        }
        __syncthreads();

        // ---- per-row stats: warp w handles rows w*8 .. w*8+7 ----
#pragma unroll
        for (int i = 0; i < 8; i++) {
            const int l = warp * 8 + i;
            const float s = As[l * 33 + lane] + Ts[lane * 65 + l];
            float mc = s;
#pragma unroll
            for (int o = 16; o > 0; o >>= 1)
                mc = fmaxf(mc, __shfl_xor_sync(0xffffffffu, mc, o));
            const float mold = m_state[l];
            const float mnew = fmaxf(mold, mc);
            float e = __expf(s - mnew);
#pragma unroll
            for (int o = 16; o > 0; o >>= 1)
                e += __shfl_xor_sync(0xffffffffu, e, o);
            if (lane == 0) {
                const float sc = __expf(mold - mnew);
                scalef[l] = sc;
                sum_state[l] = sum_state[l] * sc + e;
                m_state[l] = mnew;
            }
        }
        __syncthreads();

        // ---- rescale acc, write P into As ----
#pragma unroll
        for (int i = 0; i < 4; i++) {
            const float sc = scalef[ty * 4 + i];
#pragma unroll
            for (int j = 0; j < 4; j++) acc[i][j] *= sc;
        }
        {
            const int l = tid >> 2;
            const int r0i = (tid & 3) * 8;
            const float mv = m_state[l];
#pragma unroll
            for (int j = 0; j < 8; j++) {
                const int r = r0i + j;
                As[l * 33 + r] = __expf(As[l * 33 + r] + Ts[r * 65 + l] - mv);
            }
        }
        __syncthreads();

        // ---- P @ V ----
#pragma unroll 4
        for (int k = 0; k < 32; k++) {
            const float4 v4 = *(const float4*)&Vs[k * 68 + tx * 4];
            float p[4];
#pragma unroll
            for (int i = 0; i < 4; i++) p[i] = As[(ty * 4 + i) * 33 + k];
#pragma unroll
            for (int i = 0; i < 4; i++) {
                acc[i][0] = fmaf(p[i], v4.x, acc[i][0]);
                acc[i][1] = fmaf(p[i], v4.y, acc[i][1]);
                acc[i][2] = fmaf(p[i], v4.z, acc[i][2]);
                acc[i][3] = fmaf(p[i], v4.w, acc[i][3]);
            }
        }
        __syncthreads();
    }

    // ---- write out[b, l, h*64+d] ----
    const int b_idx = bh / HH;
    const int h     = bh % HH;
#pragma unroll
    for (int i = 0; i < 4; i++) {
        const int lrow = ty * 4 + i;
        const float inv = 1.f / sum_state[lrow];
        const int l = l0 + lrow;
        float4 r;
        r.x = acc[i][0] * inv; r.y = acc[i][1] * inv;
        r.z = acc[i][2] * inv; r.w = acc[i][3] * inv;
        *(float4*)&out[((size_t)(b_idx * LL + l)) * HIDD + h * DD + tx * 4] = r;
    }
}

// ============================================================================
// launch
// ============================================================================
extern "C" void kernel_launch(void* const* d_in, const int* in_sizes, int n_in,
                              void* d_out, int out_size)
{
    (void)in_sizes; (void)n_in; (void)out_size;
    const float* hidden = (const float*)d_in[0];
    const float* mask   = (const float*)d_in[1];
    const float* S      = (const float*)d_in[2];
    const float* Wq     = (const float*)d_in[3];
    const float* bq     = (const float*)d_in[4];
    const float* Wk     = (const float*)d_in[5];
    const float* bk     = (const float*)d_in[6];
    const float* Wv     = (const float*)d_in[7];
    const float* bv     = (const float*)d_in[8];
    float* out = (float*)d_out;

    dim3 g1(64, 12);                         // (4096/64, 768/64)
    qkv_mma_kernel<<<g1, 256>>>(hidden, Wq, bq, 0);
    qkv_mma_kernel<<<g1, 256>>>(hidden, Wk, bk, 1);
    qkv_mma_kernel<<<g1, 256>>>(hidden, Wv, bv, 2);

    dim3 g2(16, 16, 48);                     // (r tiles, l tiles, bh)
    qk_mma_kernel<<<g2, 256>>>(mask);

    dim3 g3(16, 1024);                       // (n chunks, fixed index)
    bias_mma_kernel<<<g3, 256>>>(S, 0);      // q-side, accumulate into g_scores
    bias_mma_kernel<<<g3, 256>>>(S, 1);      // k-side, write g_scoresT

    dim3 g4(16, 48);                         // (l tiles, bh)
    softmax_pv_kernel<<<g4, 256>>>(out);
}

// round 4
// speedup vs baseline: 3.3481x; 1.0760x over previous
#include <cuda_runtime.h>
#include <math.h>

#define BB   4
#define LL   1024
#define HIDD 768
#define HH   12
#define DD   64
#define BH   (BB*HH)

// ---- scratch (device globals; no allocation allowed) ----
__device__ float g_q[BH * LL * DD];                 // [bh, l, d]  (pre-scaled by 0.125)
__device__ float g_k[BH * LL * DD];                 // [bh, l, d]
__device__ float g_v[BH * LL * DD];                 // [bh, l, d]
__device__ float g_biasq[(size_t)BH * LL * LL];     // [bh, l, r]  = qS/8 + mask
__device__ float g_biaskT[(size_t)BH * LL * LL];    // [bh, r, l]  = kS/8

// ---------------- tf32 mma helpers ----------------
__device__ __forceinline__ unsigned tf32cvt(float x) {
    unsigned u;
    asm("cvt.rna.tf32.f32 %0, %1;" : "=r"(u) : "f"(x));
    return u;
}
__device__ __forceinline__ void mma_tf32(float& c0, float& c1, float& c2, float& c3,
                                         unsigned a0, unsigned a1, unsigned a2, unsigned a3,
                                         unsigned b0, unsigned b1) {
    asm("mma.sync.aligned.m16n8k8.row.col.f32.tf32.tf32.f32 "
        "{%0,%1,%2,%3},{%4,%5,%6,%7},{%8,%9},{%0,%1,%2,%3};"
        : "+f"(c0), "+f"(c1), "+f"(c2), "+f"(c3)
        : "r"(a0), "r"(a1), "r"(a2), "r"(a3), "r"(b0), "r"(b1));
}

// ============================================================================
// K1: QKV projection, tf32 mma.  blockIdx.z selects q/k/v.
// Block tile: M=64 x N=64, K-loop 768 in chunks of 64.
// ============================================================================
__global__ __launch_bounds__(256) void qkv_mma_kernel(
    const float* __restrict__ X,
    const float* __restrict__ Wq, const float* __restrict__ bq,
    const float* __restrict__ Wk, const float* __restrict__ bk,
    const float* __restrict__ Wv, const float* __restrict__ bv)
{
    __shared__ unsigned Xs[64][68];
    __shared__ unsigned Ws[64][68];

    const int which = blockIdx.z;
    const float* W    = (which == 0) ? Wq : (which == 1) ? Wk : Wv;
    const float* bias = (which == 0) ? bq : (which == 1) ? bk : bv;

    const int tid  = threadIdx.x;
    const int warp = tid >> 5;
    const int lane = tid & 31;
    const int m0 = blockIdx.x * 64;
    const int n0 = blockIdx.y * 64;
    const int mstrip = (warp & 3) * 16;
    const int nh     = (warp >> 2) * 32;

    float acc[4][4];
#pragma unroll
    for (int i = 0; i < 4; i++)
#pragma unroll
        for (int j = 0; j < 4; j++) acc[i][j] = 0.f;

    for (int k0 = 0; k0 < HIDD; k0 += 64) {
        __syncthreads();
#pragma unroll
        for (int i = 0; i < 4; i++) {
            const int idx = tid + i * 256;
            const int row = idx >> 4;
            const int c4  = idx & 15;
            float4 xv = *(const float4*)(X + (size_t)(m0 + row) * HIDD + k0 + c4 * 4);
            float4 wv = *(const float4*)(W + (size_t)(n0 + row) * HIDD + k0 + c4 * 4);
            Xs[row][c4 * 4 + 0] = tf32cvt(xv.x); Xs[row][c4 * 4 + 1] = tf32cvt(xv.y);
            Xs[row][c4 * 4 + 2] = tf32cvt(xv.z); Xs[row][c4 * 4 + 3] = tf32cvt(xv.w);
            Ws[row][c4 * 4 + 0] = tf32cvt(wv.x); Ws[row][c4 * 4 + 1] = tf32cvt(wv.y);
            Ws[row][c4 * 4 + 2] = tf32cvt(wv.z); Ws[row][c4 * 4 + 3] = tf32cvt(wv.w);
        }
        __syncthreads();
#pragma unroll
        for (int ks = 0; ks < 8; ks++) {
            const int kc = ks * 8 + (lane & 3);
            unsigned a0 = Xs[mstrip + (lane >> 2)][kc];
            unsigned a1 = Xs[mstrip + (lane >> 2) + 8][kc];
            unsigned a2 = Xs[mstrip + (lane >> 2)][kc + 4];
            unsigned a3 = Xs[mstrip + (lane >> 2) + 8][kc + 4];
#pragma unroll
            for (int nt = 0; nt < 4; nt++) {
                const int nb = nh + nt * 8;
                unsigned b0 = Ws[nb + (lane >> 2)][kc];
                unsigned b1 = Ws[nb + (lane >> 2)][kc + 4];
                mma_tf32(acc[nt][0], acc[nt][1], acc[nt][2], acc[nt][3],
                         a0, a1, a2, a3, b0, b1);
            }
        }
    }

    float* out = (which == 0) ? g_q : (which == 1) ? g_k : g_v;
    const float scale = (which == 0) ? 0.125f : 1.0f;
    const int row0 = m0 + mstrip + (lane >> 2);
#pragma unroll
    for (int nt = 0; nt < 4; nt++) {
        const int col = n0 + nh + nt * 8 + 2 * (lane & 3);
        const int h = col >> 6;
        const int d = col & 63;
#pragma unroll
        for (int half = 0; half < 2; half++) {
            const int row = row0 + half * 8;
            const int b_idx = row >> 10;
            const int l     = row & (LL - 1);
            float2 r;
            r.x = (acc[nt][2 * half + 0] + bias[col + 0]) * scale;
            r.y = (acc[nt][2 * half + 1] + bias[col + 1]) * scale;
            *(float2*)&out[(((size_t)b_idx * HH + h) * LL + l) * DD + d] = r;
        }
    }
}

// ============================================================================
// K2: structure-bias GEMMs.  For a fixed index f:
//  variant 0 (q-side, f=l): g_biasq[bh, f, n]  = q[bh,f,:] . S[f,n,:] + mask[b,n]
//  variant 1 (k-side, f=r): g_biaskT[bh, f, n] = 0.125 * k[bh,f,:] . S[n,f,:]
// M = 64 (48 real bh, 16 zero-pad), N = 64 chunk, K = 64.
// ============================================================================
__global__ __launch_bounds__(256) void bias_mma_kernel(
    const float* __restrict__ S, const float* __restrict__ mask, int variant)
{
    __shared__ unsigned As[64][68];
    __shared__ unsigned Ss[64][68];

    const int tid  = threadIdx.x;
    const int warp = tid >> 5;
    const int lane = tid & 31;
    const int n0 = blockIdx.x * 64;
    const int f  = blockIdx.y;
    const int mstrip = (warp & 3) * 16;
    const int nh     = (warp >> 2) * 32;

    const float* Aop = (variant == 0) ? g_q : g_k;

#pragma unroll
    for (int i = 0; i < 4; i++) {
        const int idx = tid + i * 256;
        const int row = idx >> 4;
        const int c4  = idx & 15;
        if (row < BH) {
            float4 av = *(const float4*)(Aop + ((size_t)row * LL + f) * DD + c4 * 4);
            As[row][c4 * 4 + 0] = tf32cvt(av.x); As[row][c4 * 4 + 1] = tf32cvt(av.y);
            As[row][c4 * 4 + 2] = tf32cvt(av.z); As[row][c4 * 4 + 3] = tf32cvt(av.w);
        } else {
            As[row][c4 * 4 + 0] = 0u; As[row][c4 * 4 + 1] = 0u;
            As[row][c4 * 4 + 2] = 0u; As[row][c4 * 4 + 3] = 0u;
        }
        size_t soff = (variant == 0)
            ? (((size_t)f * LL + n0 + row) * DD + c4 * 4)
            : (((size_t)(n0 + row) * LL + f) * DD + c4 * 4);
        float4 sv = *(const float4*)(S + soff);
        Ss[row][c4 * 4 + 0] = tf32cvt(sv.x); Ss[row][c4 * 4 + 1] = tf32cvt(sv.y);
        Ss[row][c4 * 4 + 2] = tf32cvt(sv.z); Ss[row][c4 * 4 + 3] = tf32cvt(sv.w);
    }
    __syncthreads();

    float acc[4][4];
#pragma unroll
    for (int i = 0; i < 4; i++)
#pragma unroll
        for (int j = 0; j < 4; j++) acc[i][j] = 0.f;

#pragma unroll
    for (int ks = 0; ks < 8; ks++) {
        const int kc = ks * 8 + (lane & 3);
        unsigned a0 = As[mstrip + (lane >> 2)][kc];
        unsigned a1 = As[mstrip + (lane >> 2) + 8][kc];
        unsigned a2 = As[mstrip + (lane >> 2)][kc + 4];
        unsigned a3 = As[mstrip + (lane >> 2) + 8][kc + 4];
#pragma unroll
        for (int nt = 0; nt < 4; nt++) {
            const int nb = nh + nt * 8;
            unsigned b0 = Ss[nb + (lane >> 2)][kc];
            unsigned b1 = Ss[nb + (lane >> 2)][kc + 4];
            mma_tf32(acc[nt][0], acc[nt][1], acc[nt][2], acc[nt][3],
                     a0, a1, a2, a3, b0, b1);
        }
    }

    const int row0 = mstrip + (lane >> 2);   // bh index
#pragma unroll
    for (int nt = 0; nt < 4; nt++) {
        const int col = n0 + nh + nt * 8 + 2 * (lane & 3);
#pragma unroll
        for (int half = 0; half < 2; half++) {
            const int bh = row0 + half * 8;
            if (bh >= BH) continue;
            float2 r;
            if (variant == 0) {
                const int b_idx = bh / HH;
                r.x = acc[nt][2 * half + 0] + mask[b_idx * LL + col + 0];
                r.y = acc[nt][2 * half + 1] + mask[b_idx * LL + col + 1];
                *(float2*)&g_biasq[((size_t)bh * LL + f) * LL + col] = r;
            } else {
                r.x = acc[nt][2 * half + 0] * 0.125f;
                r.y = acc[nt][2 * half + 1] * 0.125f;
                *(float2*)&g_biaskT[((size_t)bh * LL + f) * LL + col] = r;
            }
        }
    }
}

// ============================================================================
// K3: fused flash attention.  Block = (bh, 64 l-rows), r-chunks of 32.
// s = (q.k via mma) + biasq[l,r] + biaskT[r,l]; online softmax; P@V via mma
// with error compensation (P = Phi+Plo, V = Vh+Vl; 3 mmas).
// Dynamic smem (~71 KB).
// ============================================================================
#define RC      32
#define SPW     36    // Sp/Pl row stride
#define QSW     68    // tf32 tile row stride

#define OFF_QS  0                       // 64*68   = 4352
#define OFF_KS  (OFF_QS + 64*QSW)       // 32*68   = 2176
#define OFF_VH  (OFF_KS + RC*QSW)
#define OFF_VL  (OFF_VH + RC*QSW)
#define OFF_TS  (OFF_VL + RC*QSW)       // 32*65   = 2080
#define OFF_SP  (OFF_TS + RC*65)        // 64*36   = 2304
#define OFF_PL  (OFF_SP + 64*SPW)
#define OFF_MS  (OFF_PL + 64*SPW)       // 64
#define OFF_SU  (OFF_MS + 64)           // 64
#define OFF_SC  (OFF_SU + 64)           // 64
#define SMEM_FLOATS (OFF_SC + 64)       // 17760 floats = 71040 B

__global__ __launch_bounds__(256) void fused_attn_kernel(float* __restrict__ out)
{
    extern __shared__ float sm[];
    float* Qs = sm + OFF_QS;   // tf32 bits
    float* Ks = sm + OFF_KS;   // tf32 bits
    float* Vh = sm + OFF_VH;   // tf32 bits
    float* Vl = sm + OFF_VL;   // tf32 bits
    float* Ts = sm + OFF_TS;   // float, [r][l] stride 65
    float* Sp = sm + OFF_SP;   // float s, later tf32 Phi bits
    float* Pl = sm + OFF_PL;   // tf32 Plo bits
    float* m_state   = sm + OFF_MS;
    float* sum_state = sm + OFF_SU;
    float* scalef    = sm + OFF_SC;

    const int tid  = threadIdx.x;
    const int warp = tid >> 5;
    const int lane = tid & 31;
    const int bh   = blockIdx.y;
    const int l0   = blockIdx.x * 64;

    const int mstrip = (warp & 3) * 16;
    const int nh2    = (warp >> 2) * 16;   // qk N = 32
    const int nhpv   = (warp >> 2) * 32;   // pv N = 64
    const int arow   = mstrip + (lane >> 2);
    const int kcl    = lane & 3;

    // load Q tile once (tf32)
#pragma unroll
    for (int i = 0; i < 4; i++) {
        const int idx = tid + i * 256;
        const int row = idx >> 4;
        const int c4  = idx & 15;
        float4 qv = *(const float4*)(g_q + ((size_t)bh * LL + l0 + row) * DD + c4 * 4);
        Qs[row * QSW + c4 * 4 + 0] = __uint_as_float(tf32cvt(qv.x));
        Qs[row * QSW + c4 * 4 + 1] = __uint_as_float(tf32cvt(qv.y));
        Qs[row * QSW + c4 * 4 + 2] = __uint_as_float(tf32cvt(qv.z));
        Qs[row * QSW + c4 * 4 + 3] = __uint_as_float(tf32cvt(qv.w));
    }
    if (tid < 64) { m_state[tid] = -1e30f; sum_state[tid] = 0.f; }

    float accpv[4][4];
#pragma unroll
    for (int i = 0; i < 4; i++)
#pragma unroll
        for (int j = 0; j < 4; j++) accpv[i][j] = 0.f;

    for (int rc = 0; rc < LL; rc += RC) {
        __syncthreads();
        // ---- K and V chunks (tf32 + residual) ----
#pragma unroll
        for (int i = 0; i < 2; i++) {
            const int idx = tid + i * 256;
            const int row = idx >> 4;     // 0..31
            const int c4  = idx & 15;
            float4 kv = *(const float4*)(g_k + ((size_t)bh * LL + rc + row) * DD + c4 * 4);
            float4 vv = *(const float4*)(g_v + ((size_t)bh * LL + rc + row) * DD + c4 * 4);
            Ks[row * QSW + c4 * 4 + 0] = __uint_as_float(tf32cvt(kv.x));
            Ks[row * QSW + c4 * 4 + 1] = __uint_as_float(tf32cvt(kv.y));
            Ks[row * QSW + c4 * 4 + 2] = __uint_as_float(tf32cvt(kv.z));
            Ks[row * QSW + c4 * 4 + 3] = __uint_as_float(tf32cvt(kv.w));
            const float vf[4] = { vv.x, vv.y, vv.z, vv.w };
#pragma unroll
            for (int j = 0; j < 4; j++) {
                unsigned hi = tf32cvt(vf[j]);
                float hif = __uint_as_float(hi);
                Vh[row * QSW + c4 * 4 + j] = hif;
                Vl[row * QSW + c4 * 4 + j] = __uint_as_float(tf32cvt(vf[j] - hif));
            }
        }
        // ---- biaskT chunk: Ts[r][l] ----
#pragma unroll
        for (int i = 0; i < 8; i++) {
            const int idx = tid + i * 256;
            const int row = idx >> 6;     // r
            const int col = idx & 63;     // l
            Ts[row * 65 + col] =
                g_biaskT[((size_t)bh * LL + rc + row) * LL + l0 + col];
        }
        // ---- biasq chunk into Sp[l][r] ----
#pragma unroll
        for (int i = 0; i < 8; i++) {
            const int idx = tid + i * 256;
            const int row = idx >> 5;     // l
            const int col = idx & 31;     // r
            Sp[row * SPW + col] =
                g_biasq[((size_t)bh * LL + l0 + row) * LL + rc + col];
        }
        __syncthreads();

        // ---- qk mma ----
        float accqk[2][4];
#pragma unroll
        for (int i = 0; i < 2; i++)
#pragma unroll
            for (int j = 0; j < 4; j++) accqk[i][j] = 0.f;
#pragma unroll
        for (int ks = 0; ks < 8; ks++) {
            const int kc = ks * 8 + kcl;
            unsigned a0 = __float_as_uint(Qs[arow * QSW + kc]);
            unsigned a1 = __float_as_uint(Qs[(arow + 8) * QSW + kc]);
            unsigned a2 = __float_as_uint(Qs[arow * QSW + kc + 4]);
            unsigned a3 = __float_as_uint(Qs[(arow + 8) * QSW + kc + 4]);
#pragma unroll
            for (int nt = 0; nt < 2; nt++) {
                const int nb = nh2 + nt * 8;
                unsigned b0 = __float_as_uint(Ks[(nb + (lane >> 2)) * QSW + kc]);
                unsigned b1 = __float_as_uint(Ks[(nb + (lane >> 2)) * QSW + kc + 4]);
                mma_tf32(accqk[nt][0], accqk[nt][1], accqk[nt][2], accqk[nt][3],
                         a0, a1, a2, a3, b0, b1);
            }
        }
        // epilogue: Sp[l][r] += qk + Ts[r][l]
#pragma unroll
        for (int nt = 0; nt < 2; nt++) {
            const int col = nh2 + nt * 8 + 2 * (lane & 3);
#pragma unroll
            for (int half = 0; half < 2; half++) {
                const int row = arow + half * 8;
                Sp[row * SPW + col]     += accqk[nt][2 * half + 0] + Ts[(col)     * 65 + row];
                Sp[row * SPW + col + 1] += accqk[nt][2 * half + 1] + Ts[(col + 1) * 65 + row];
            }
        }
        __syncthreads();

        // ---- online stats: warp w owns rows w*8..w*8+7 ----
#pragma unroll
        for (int i = 0; i < 8; i++) {
            const int l = warp * 8 + i;
            const float s = Sp[l * SPW + lane];
            float mc = s;
#pragma unroll
            for (int o = 16; o > 0; o >>= 1)
                mc = fmaxf(mc, __shfl_xor_sync(0xffffffffu, mc, o));
            const float mold = m_state[l];
            const float mnew = fmaxf(mold, mc);
            float e = __expf(s - mnew);
#pragma unroll
            for (int o = 16; o > 0; o >>= 1)
                e += __shfl_xor_sync(0xffffffffu, e, o);
            if (lane == 0) {
                const float sc = __expf(mold - mnew);
                scalef[l] = sc;
                sum_state[l] = sum_state[l] * sc + e;
                m_state[l] = mnew;
            }
        }
        __syncthreads();

        // ---- rescale pv acc ----
        {
            const float sc0 = scalef[arow];
            const float sc1 = scalef[arow + 8];
#pragma unroll
            for (int nt = 0; nt < 4; nt++) {
                accpv[nt][0] *= sc0; accpv[nt][1] *= sc0;
                accpv[nt][2] *= sc1; accpv[nt][3] *= sc1;
            }
        }
        // ---- P (hi/lo tf32) ----
        {
            const int l = tid >> 2;
            const int r0i = (tid & 3) * 8;
            const float mv = m_state[l];
#pragma unroll
            for (int j = 0; j < 8; j++) {
                const int r = r0i + j;
                const float p = __expf(Sp[l * SPW + r] - mv);
                unsigned hi = tf32cvt(p);
                float hif = __uint_as_float(hi);
                Sp[l * SPW + r] = hif;
                Pl[l * SPW + r] = __uint_as_float(tf32cvt(p - hif));
            }
        }
        __syncthreads();

        // ---- P @ V mma (compensated) ----
#pragma unroll
        for (int ks = 0; ks < 4; ks++) {
            const int kc = ks * 8 + kcl;
            unsigned ah0 = __float_as_uint(Sp[arow * SPW + kc]);
            unsigned ah1 = __float_as_uint(Sp[(arow + 8) * SPW + kc]);
            unsigned ah2 = __float_as_uint(Sp[arow * SPW + kc + 4]);
            unsigned ah3 = __float_as_uint(Sp[(arow + 8) * SPW + kc + 4]);
            unsigned al0 = __float_as_uint(Pl[arow * SPW + kc]);
            unsigned al1 = __float_as_uint(Pl[(arow + 8) * SPW + kc]);
            unsigned al2 = __float_as_uint(Pl[arow * SPW + kc + 4]);
            unsigned al3 = __float_as_uint(Pl[(arow + 8) * SPW + kc + 4]);
#pragma unroll
            for (int nt = 0; nt < 4; nt++) {
                const int nb = nhpv + nt * 8 + (lane >> 2);
                unsigned bh0 = __float_as_uint(Vh[(ks * 8 + kcl) * QSW + nb]);
                unsigned bh1 = __float_as_uint(Vh[(ks * 8 + kcl + 4) * QSW + nb]);
                unsigned bl0 = __float_as_uint(Vl[(ks * 8 + kcl) * QSW + nb]);
                unsigned bl1 = __float_as_uint(Vl[(ks * 8 + kcl + 4) * QSW + nb]);
                mma_tf32(accpv[nt][0], accpv[nt][1], accpv[nt][2], accpv[nt][3],
                         ah0, ah1, ah2, ah3, bh0, bh1);
                mma_tf32(accpv[nt][0], accpv[nt][1], accpv[nt][2], accpv[nt][3],
                         al0, al1, al2, al3, bh0, bh1);
                mma_tf32(accpv[nt][0], accpv[nt][1], accpv[nt][2], accpv[nt][3],
                         ah0, ah1, ah2, ah3, bl0, bl1);
            }
        }
    }
    __syncthreads();

    // ---- write out[b, l, h*64 + d] ----
    const int b_idx = bh / HH;
    const int h     = bh % HH;
#pragma unroll
    for (int half = 0; half < 2; half++) {
        const int row = arow + half * 8;
        const float inv = 1.f / sum_state[row];
        const int l = l0 + row;
#pragma unroll
        for (int nt = 0; nt < 4; nt++) {
            const int col = nhpv + nt * 8 + 2 * (lane & 3);
            float2 r;
            r.x = accpv[nt][2 * half + 0] * inv;
            r.y = accpv[nt][2 * half + 1] * inv;
            *(float2*)&out[((size_t)(b_idx * LL + l)) * HIDD + h * DD + col] = r;
        }
    }
}

// ============================================================================
// launch
// ============================================================================
extern "C" void kernel_launch(void* const* d_in, const int* in_sizes, int n_in,
                              void* d_out, int out_size)
{
    (void)in_sizes; (void)n_in; (void)out_size;
    const float* hidden = (const float*)d_in[0];
    const float* mask   = (const float*)d_in[1];
    const float* S      = (const float*)d_in[2];
    const float* Wq     = (const float*)d_in[3];
    const float* bq     = (const float*)d_in[4];
    const float* Wk     = (const float*)d_in[5];
    const float* bk     = (const float*)d_in[6];
    const float* Wv     = (const float*)d_in[7];
    const float* bv     = (const float*)d_in[8];
    float* out = (float*)d_out;

    static int smem_set = 0;
    if (!smem_set) {
        cudaFuncSetAttribute(fused_attn_kernel,
                             cudaFuncAttributeMaxDynamicSharedMemorySize,
                             SMEM_FLOATS * (int)sizeof(float));
        smem_set = 1;
    }

    dim3 g1(64, 12, 3);
    qkv_mma_kernel<<<g1, 256>>>(hidden, Wq, bq, Wk, bk, Wv, bv);

    dim3 g2(16, 1024);
    bias_mma_kernel<<<g2, 256>>>(S, mask, 0);   // q-side -> g_biasq (+mask)
    bias_mma_kernel<<<g2, 256>>>(S, mask, 1);   // k-side -> g_biaskT

    dim3 g3(16, 48);
    fused_attn_kernel<<<g3, 256, SMEM_FLOATS * sizeof(float)>>>(out);
}

// round 6
// speedup vs baseline: 4.3161x; 1.2891x over previous
#include <cuda_runtime.h>
#include <cuda_bf16.h>
#include <math.h>

#define BB   4
#define LL   1024
#define HIDD 768
#define HH   12
#define DD   64
#define BH   (BB*HH)

// ---- scratch (device globals; no allocation allowed) ----
__device__ float g_q[BH * LL * DD];                        // [bh, l, d] (pre-scaled 0.125)
__device__ float g_k[BH * LL * DD];                        // [bh, l, d]
__device__ float g_v[BH * LL * DD];                        // [bh, l, d]
__device__ __nv_bfloat16 g_biasq[(size_t)BH * LL * LL];    // [bh, l, r] = qS/8 + mask
__device__ __nv_bfloat16 g_biaskT[(size_t)BH * LL * LL];   // [bh, r, l] = kS/8

// ---------------- helpers ----------------
__device__ __forceinline__ unsigned tf32cvt(float x) {
    unsigned u;
    asm("cvt.rna.tf32.f32 %0, %1;" : "=r"(u) : "f"(x));
    return u;
}
__device__ __forceinline__ void mma_tf32(float& c0, float& c1, float& c2, float& c3,
                                         unsigned a0, unsigned a1, unsigned a2, unsigned a3,
                                         unsigned b0, unsigned b1) {
    asm("mma.sync.aligned.m16n8k8.row.col.f32.tf32.tf32.f32 "
        "{%0,%1,%2,%3},{%4,%5,%6,%7},{%8,%9},{%0,%1,%2,%3};"
        : "+f"(c0), "+f"(c1), "+f"(c2), "+f"(c3)
        : "r"(a0), "r"(a1), "r"(a2), "r"(a3), "r"(b0), "r"(b1));
}
__device__ __forceinline__ void cp16(const void* smem_dst, const void* gsrc) {
    unsigned sa = (unsigned)__cvta_generic_to_shared(smem_dst);
    asm volatile("cp.async.cg.shared.global [%0], [%1], 16;" :: "r"(sa), "l"(gsrc));
}

// ============================================================================
// K1: QKV projection, tf32 mma.  blockIdx.z selects q/k/v.
// ============================================================================
__global__ __launch_bounds__(256) void qkv_mma_kernel(
    const float* __restrict__ X,
    const float* __restrict__ Wq, const float* __restrict__ bq,
    const float* __restrict__ Wk, const float* __restrict__ bk,
    const float* __restrict__ Wv, const float* __restrict__ bv)
{
    __shared__ unsigned Xs[64][68];
    __shared__ unsigned Ws[64][68];

    const int which = blockIdx.z;
    const float* W    = (which == 0) ? Wq : (which == 1) ? Wk : Wv;
    const float* bias = (which == 0) ? bq : (which == 1) ? bk : bv;

    const int tid  = threadIdx.x;
    const int warp = tid >> 5;
    const int lane = tid & 31;
    const int m0 = blockIdx.x * 64;
    const int n0 = blockIdx.y * 64;
    const int mstrip = (warp & 3) * 16;
    const int nh     = (warp >> 2) * 32;

    float acc[4][4];
#pragma unroll
    for (int i = 0; i < 4; i++)
#pragma unroll
        for (int j = 0; j < 4; j++) acc[i][j] = 0.f;

    for (int k0 = 0; k0 < HIDD; k0 += 64) {
        __syncthreads();
#pragma unroll
        for (int i = 0; i < 4; i++) {
            const int idx = tid + i * 256;
            const int row = idx >> 4;
            const int c4  = idx & 15;
            float4 xv = *(const float4*)(X + (size_t)(m0 + row) * HIDD + k0 + c4 * 4);
            float4 wv = *(const float4*)(W + (size_t)(n0 + row) * HIDD + k0 + c4 * 4);
            Xs[row][c4 * 4 + 0] = tf32cvt(xv.x); Xs[row][c4 * 4 + 1] = tf32cvt(xv.y);
            Xs[row][c4 * 4 + 2] = tf32cvt(xv.z); Xs[row][c4 * 4 + 3] = tf32cvt(xv.w);
            Ws[row][c4 * 4 + 0] = tf32cvt(wv.x); Ws[row][c4 * 4 + 1] = tf32cvt(wv.y);
            Ws[row][c4 * 4 + 2] = tf32cvt(wv.z); Ws[row][c4 * 4 + 3] = tf32cvt(wv.w);
        }
        __syncthreads();
#pragma unroll
        for (int ks = 0; ks < 8; ks++) {
            const int kc = ks * 8 + (lane & 3);
            unsigned a0 = Xs[mstrip + (lane >> 2)][kc];
            unsigned a1 = Xs[mstrip + (lane >> 2) + 8][kc];
            unsigned a2 = Xs[mstrip + (lane >> 2)][kc + 4];
            unsigned a3 = Xs[mstrip + (lane >> 2) + 8][kc + 4];
#pragma unroll
            for (int nt = 0; nt < 4; nt++) {
                const int nb = nh + nt * 8;
                unsigned b0 = Ws[nb + (lane >> 2)][kc];
                unsigned b1 = Ws[nb + (lane >> 2)][kc + 4];
                mma_tf32(acc[nt][0], acc[nt][1], acc[nt][2], acc[nt][3],
                         a0, a1, a2, a3, b0, b1);
            }
        }
    }

    float* out = (which == 0) ? g_q : (which == 1) ? g_k : g_v;
    const float scale = (which == 0) ? 0.125f : 1.0f;
    const int row0 = m0 + mstrip + (lane >> 2);
#pragma unroll
    for (int nt = 0; nt < 4; nt++) {
        const int col = n0 + nh + nt * 8 + 2 * (lane & 3);
        const int h = col >> 6;
        const int d = col & 63;
#pragma unroll
        for (int half = 0; half < 2; half++) {
            const int row = row0 + half * 8;
            const int b_idx = row >> 10;
            const int l     = row & (LL - 1);
            float2 r;
            r.x = (acc[nt][2 * half + 0] + bias[col + 0]) * scale;
            r.y = (acc[nt][2 * half + 1] + bias[col + 1]) * scale;
            *(float2*)&out[(((size_t)b_idx * HH + h) * LL + l) * DD + d] = r;
        }
    }
}

// ============================================================================
// K2: structure-bias GEMMs (bf16 output).
//  variant 0 (f=l): g_biasq[bh, f, n]  = q[bh,f,:].S[f,n,:] + mask[b,n]
//  variant 1 (f=r): g_biaskT[bh, f, n] = 0.125 * k[bh,f,:].S[n,f,:]
// ============================================================================
__global__ __launch_bounds__(256) void bias_mma_kernel(
    const float* __restrict__ S, const float* __restrict__ mask, int variant)
{
    __shared__ unsigned As[64][68];
    __shared__ unsigned Ss[64][68];

    const int tid  = threadIdx.x;
    const int warp = tid >> 5;
    const int lane = tid & 31;
    const int n0 = blockIdx.x * 64;
    const int f  = blockIdx.y;
    const int mstrip = (warp & 3) * 16;
    const int nh     = (warp >> 2) * 32;

    const float* Aop = (variant == 0) ? g_q : g_k;

#pragma unroll
    for (int i = 0; i < 4; i++) {
        const int idx = tid + i * 256;
        const int row = idx >> 4;
        const int c4  = idx & 15;
        if (row < BH) {
            float4 av = *(const float4*)(Aop + ((size_t)row * LL + f) * DD + c4 * 4);
            As[row][c4 * 4 + 0] = tf32cvt(av.x); As[row][c4 * 4 + 1] = tf32cvt(av.y);
            As[row][c4 * 4 + 2] = tf32cvt(av.z); As[row][c4 * 4 + 3] = tf32cvt(av.w);
        } else {
            As[row][c4 * 4 + 0] = 0u; As[row][c4 * 4 + 1] = 0u;
            As[row][c4 * 4 + 2] = 0u; As[row][c4 * 4 + 3] = 0u;
        }
        size_t soff = (variant == 0)
            ? (((size_t)f * LL + n0 + row) * DD + c4 * 4)
            : (((size_t)(n0 + row) * LL + f) * DD + c4 * 4);
        float4 sv = *(const float4*)(S + soff);
        Ss[row][c4 * 4 + 0] = tf32cvt(sv.x); Ss[row][c4 * 4 + 1] = tf32cvt(sv.y);
        Ss[row][c4 * 4 + 2] = tf32cvt(sv.z); Ss[row][c4 * 4 + 3] = tf32cvt(sv.w);
    }
    __syncthreads();

    float acc[4][4];
#pragma unroll
    for (int i = 0; i < 4; i++)
#pragma unroll
        for (int j = 0; j < 4; j++) acc[i][j] = 0.f;

#pragma unroll
    for (int ks = 0; ks < 8; ks++) {
        const int kc = ks * 8 + (lane & 3);
        unsigned a0 = As[mstrip + (lane >> 2)][kc];
        unsigned a1 = As[mstrip + (lane >> 2) + 8][kc];
        unsigned a2 = As[mstrip + (lane >> 2)][kc + 4];
        unsigned a3 = As[mstrip + (lane >> 2) + 8][kc + 4];
#pragma unroll
        for (int nt = 0; nt < 4; nt++) {
            const int nb = nh + nt * 8;
            unsigned b0 = Ss[nb + (lane >> 2)][kc];
            unsigned b1 = Ss[nb + (lane >> 2)][kc + 4];
            mma_tf32(acc[nt][0], acc[nt][1], acc[nt][2], acc[nt][3],
                     a0, a1, a2, a3, b0, b1);
        }
    }

    const int row0 = mstrip + (lane >> 2);   // bh index
#pragma unroll
    for (int nt = 0; nt < 4; nt++) {
        const int col = n0 + nh + nt * 8 + 2 * (lane & 3);
#pragma unroll
        for (int half = 0; half < 2; half++) {
            const int bh = row0 + half * 8;
            if (bh >= BH) continue;
            if (variant == 0) {
                const int b_idx = bh / HH;
                __nv_bfloat162 bv = __floats2bfloat162_rn(
                    acc[nt][2 * half + 0] + mask[b_idx * LL + col + 0],
                    acc[nt][2 * half + 1] + mask[b_idx * LL + col + 1]);
                *(__nv_bfloat162*)&g_biasq[((size_t)bh * LL + f) * LL + col] = bv;
            } else {
                __nv_bfloat162 bv = __floats2bfloat162_rn(
                    acc[nt][2 * half + 0] * 0.125f,
                    acc[nt][2 * half + 1] * 0.125f);
                *(__nv_bfloat162*)&g_biaskT[((size_t)bh * LL + f) * LL + col] = bv;
            }
        }
    }
}

// ============================================================================
// K3: fused flash attention, cp.async double-buffered (race-free ordering:
// wait -> syncthreads -> issue next stage).  P@V compensated (3 mmas).
// ============================================================================
#define RC      32
#define SPW     36
#define QSW     68

// smem layout (float units)
#define OFF_QS    0                       // 64*68 = 4352
#define OFF_KS0   4352                    // 32*68 = 2176
#define OFF_KS1   6528
#define OFF_VR0   8704
#define OFF_VR1   10880
#define OFF_SP    13056                   // 64*36 = 2304
#define OFF_PL    15360                   // 64*36 = 2304
#define OFF_BQ0   17664                   // 64*40 bf16 = 1280 floats
#define OFF_BQ1   18944
#define OFF_TS    20224                   // 64*34 bf16 = 1088 floats
#define OFF_MS    21312
#define OFF_SU    21376
#define OFF_SC    21440
#define SMEM_FLOATS 21504                 // 86016 B

__global__ __launch_bounds__(256) void fused_attn_kernel(float* __restrict__ out)
{
    extern __shared__ float sm[];
    float* Qs = sm + OFF_QS;
    float* Sp = sm + OFF_SP;
    float* Pl = sm + OFF_PL;
    float* m_state   = sm + OFF_MS;
    float* sum_state = sm + OFF_SU;
    float* scalef    = sm + OFF_SC;

    const int tid  = threadIdx.x;
    const int warp = tid >> 5;
    const int lane = tid & 31;
    const int bh   = blockIdx.y;
    const int l0   = blockIdx.x * 64;

    const int mstrip = (warp & 3) * 16;
    const int nh2    = (warp >> 2) * 16;   // qk N = 32
    const int nhpv   = (warp >> 2) * 32;   // pv N = 64
    const int arow   = mstrip + (lane >> 2);
    const int kcl    = lane & 3;

    // ---- prologue: Q tile -> tf32 smem ----
#pragma unroll
    for (int i = 0; i < 4; i++) {
        const int idx = tid + i * 256;
        const int row = idx >> 4;
        const int c4  = idx & 15;
        float4 qv = *(const float4*)(g_q + ((size_t)bh * LL + l0 + row) * DD + c4 * 4);
        Qs[row * QSW + c4 * 4 + 0] = __uint_as_float(tf32cvt(qv.x));
        Qs[row * QSW + c4 * 4 + 1] = __uint_as_float(tf32cvt(qv.y));
        Qs[row * QSW + c4 * 4 + 2] = __uint_as_float(tf32cvt(qv.z));
        Qs[row * QSW + c4 * 4 + 3] = __uint_as_float(tf32cvt(qv.w));
    }
    if (tid < 64) { m_state[tid] = -1e30f; sum_state[tid] = 0.f; }

    // staging index decomposition (all 256 threads)
    const int krow = tid >> 4, kseg = tid & 15;            // K/V
    const int brow = tid >> 2, bseg = tid & 3;             // Bq
    const int trow = tid >> 3, tseg = tid & 7;             // Ts LDG

    auto stage = [&](int rc, int db) {
        float* Ks = sm + (db ? OFF_KS1 : OFF_KS0);
        float* Vr = sm + (db ? OFF_VR1 : OFF_VR0);
        __nv_bfloat16* Bq = (__nv_bfloat16*)(sm + (db ? OFF_BQ1 : OFF_BQ0));
#pragma unroll
        for (int i = 0; i < 2; i++) {
            const int row = krow + i * 16;
            cp16(&Ks[row * QSW + kseg * 4], g_k + ((size_t)bh * LL + rc + row) * DD + kseg * 4);
            cp16(&Vr[row * QSW + kseg * 4], g_v + ((size_t)bh * LL + rc + row) * DD + kseg * 4);
        }
        cp16(&Bq[brow * 40 + bseg * 8],
             g_biasq + ((size_t)bh * LL + l0 + brow) * LL + rc + bseg * 8);
        asm volatile("cp.async.commit_group;" ::: "memory");
    };
    auto ldg_ts = [&](int rc) -> uint4 {
        return *(const uint4*)(g_biaskT + ((size_t)bh * LL + rc + trow) * LL + l0 + tseg * 8);
    };

    float accpv[4][4];
#pragma unroll
    for (int i = 0; i < 4; i++)
#pragma unroll
        for (int j = 0; j < 4; j++) accpv[i][j] = 0.f;

    uint4 ts_reg = ldg_ts(0);
    stage(0, 0);

    for (int ci = 0; ci < LL / RC; ci++) {
        const int cur = ci & 1;
        float* Ks = sm + (cur ? OFF_KS1 : OFF_KS0);
        float* Vr = sm + (cur ? OFF_VR1 : OFF_VR0);
        __nv_bfloat16* Bq = (__nv_bfloat16*)(sm + (cur ? OFF_BQ1 : OFF_BQ0));
        unsigned short* TsL = (unsigned short*)(sm + OFF_TS);

        // wait for chunk `cur`, THEN barrier: publishes cur to all threads AND
        // guarantees everyone finished reading buffer cur^1 (prev chunk).
        asm volatile("cp.async.wait_group 0;" ::: "memory");
        __syncthreads();

        // only now is it safe to overwrite buffer cur^1 with chunk ci+1
        uint4 ts_next;
        if (ci + 1 < LL / RC) {
            ts_next = ldg_ts((ci + 1) * RC);
            stage((ci + 1) * RC, cur ^ 1);
        }

        // Ts transpose store: TsL[l][r], stride 34 halfwords
        {
            const unsigned short* h = (const unsigned short*)&ts_reg;
#pragma unroll
            for (int j = 0; j < 8; j++)
                TsL[(tseg * 8 + j) * 34 + trow] = h[j];
        }

        // ---- qk mma (K cvt on the fly) ----
        float accqk[2][4];
#pragma unroll
        for (int i = 0; i < 2; i++)
#pragma unroll
            for (int j = 0; j < 4; j++) accqk[i][j] = 0.f;
#pragma unroll
        for (int ks = 0; ks < 8; ks++) {
            const int kc = ks * 8 + kcl;
            unsigned a0 = __float_as_uint(Qs[arow * QSW + kc]);
            unsigned a1 = __float_as_uint(Qs[(arow + 8) * QSW + kc]);
            unsigned a2 = __float_as_uint(Qs[arow * QSW + kc + 4]);
            unsigned a3 = __float_as_uint(Qs[(arow + 8) * QSW + kc + 4]);
#pragma unroll
            for (int nt = 0; nt < 2; nt++) {
                const int nb = nh2 + nt * 8 + (lane >> 2);
                unsigned b0 = tf32cvt(Ks[nb * QSW + kc]);
                unsigned b1 = tf32cvt(Ks[nb * QSW + kc + 4]);
                mma_tf32(accqk[nt][0], accqk[nt][1], accqk[nt][2], accqk[nt][3],
                         a0, a1, a2, a3, b0, b1);
            }
        }
#pragma unroll
        for (int nt = 0; nt < 2; nt++) {
            const int col = nh2 + nt * 8 + 2 * (lane & 3);
#pragma unroll
            for (int half = 0; half < 2; half++) {
                const int row = arow + half * 8;
                *(float2*)&Sp[row * SPW + col] =
                    make_float2(accqk[nt][2 * half + 0], accqk[nt][2 * half + 1]);
            }
        }
        __syncthreads();                    // Sp + TsL ready

        // ---- merged stats + P (thread owns l = tid>>2, r = (tid&3)*8 .. +7) ----
        {
            const int l  = tid >> 2;
            const int c0 = (tid & 3) * 8;
            const float mv_old = m_state[l];
            float s[8];
            {
                float4 sp0 = *(float4*)&Sp[l * SPW + c0];
                float4 sp1 = *(float4*)&Sp[l * SPW + c0 + 4];
                const __nv_bfloat162* bq2 = (const __nv_bfloat162*)&Bq[l * 40 + c0];
                const __nv_bfloat162* ts2 = (const __nv_bfloat162*)&TsL[l * 34 + c0];
                float2 b0 = __bfloat1622float2(bq2[0]);
                float2 b1 = __bfloat1622float2(bq2[1]);
                float2 b2 = __bfloat1622float2(bq2[2]);
                float2 b3 = __bfloat1622float2(bq2[3]);
                float2 t0 = __bfloat1622float2(ts2[0]);
                float2 t1 = __bfloat1622float2(ts2[1]);
                float2 t2 = __bfloat1622float2(ts2[2]);
                float2 t3 = __bfloat1622float2(ts2[3]);
                s[0] = sp0.x + b0.x + t0.x;  s[1] = sp0.y + b0.y + t0.y;
                s[2] = sp0.z + b1.x + t1.x;  s[3] = sp0.w + b1.y + t1.y;
                s[4] = sp1.x + b2.x + t2.x;  s[5] = sp1.y + b2.y + t2.y;
                s[6] = sp1.z + b3.x + t3.x;  s[7] = sp1.w + b3.y + t3.y;
            }
            float mc = s[0];
#pragma unroll
            for (int j = 1; j < 8; j++) mc = fmaxf(mc, s[j]);
            mc = fmaxf(mc, __shfl_xor_sync(0xffffffffu, mc, 1));
            mc = fmaxf(mc, __shfl_xor_sync(0xffffffffu, mc, 2));
            const float mnew = fmaxf(mv_old, mc);
            float e = 0.f;
            float pv[8], ph[8];
#pragma unroll
            for (int j = 0; j < 8; j++) {
                pv[j] = __expf(s[j] - mnew);
                e += pv[j];
                ph[j] = __uint_as_float(tf32cvt(pv[j]));
            }
            // store P hi (tf32 bits) and P lo (tf32 of residual)
            float4 p0, p1, q0, q1;
            p0.x = ph[0]; p0.y = ph[1]; p0.z = ph[2]; p0.w = ph[3];
            p1.x = ph[4]; p1.y = ph[5]; p1.z = ph[6]; p1.w = ph[7];
            q0.x = __uint_as_float(tf32cvt(pv[0] - ph[0]));
            q0.y = __uint_as_float(tf32cvt(pv[1] - ph[1]));
            q0.z = __uint_as_float(tf32cvt(pv[2] - ph[2]));
            q0.w = __uint_as_float(tf32cvt(pv[3] - ph[3]));
            q1.x = __uint_as_float(tf32cvt(pv[4] - ph[4]));
            q1.y = __uint_as_float(tf32cvt(pv[5] - ph[5]));
            q1.z = __uint_as_float(tf32cvt(pv[6] - ph[6]));
            q1.w = __uint_as_float(tf32cvt(pv[7] - ph[7]));
            *(float4*)&Sp[l * SPW + c0]     = p0;
            *(float4*)&Sp[l * SPW + c0 + 4] = p1;
            *(float4*)&Pl[l * SPW + c0]     = q0;
            *(float4*)&Pl[l * SPW + c0 + 4] = q1;
            e += __shfl_xor_sync(0xffffffffu, e, 1);
            e += __shfl_xor_sync(0xffffffffu, e, 2);
            if ((tid & 3) == 0) {
                const float sc = __expf(mv_old - mnew);
                scalef[l] = sc;
                sum_state[l] = sum_state[l] * sc + e;
                m_state[l] = mnew;
            }
        }
        __syncthreads();                    // P + scalef ready

        // ---- rescale + compensated P@V mma (V split on the fly) ----
        {
            const float sc0 = scalef[arow];
            const float sc1 = scalef[arow + 8];
#pragma unroll
            for (int nt = 0; nt < 4; nt++) {
                accpv[nt][0] *= sc0; accpv[nt][1] *= sc0;
                accpv[nt][2] *= sc1; accpv[nt][3] *= sc1;
            }
        }
#pragma unroll
        for (int ks = 0; ks < 4; ks++) {
            const int kc = ks * 8 + kcl;
            unsigned ah0 = __float_as_uint(Sp[arow * SPW + kc]);
            unsigned ah1 = __float_as_uint(Sp[(arow + 8) * SPW + kc]);
            unsigned ah2 = __float_as_uint(Sp[arow * SPW + kc + 4]);
            unsigned ah3 = __float_as_uint(Sp[(arow + 8) * SPW + kc + 4]);
            unsigned al0 = __float_as_uint(Pl[arow * SPW + kc]);
            unsigned al1 = __float_as_uint(Pl[(arow + 8) * SPW + kc]);
            unsigned al2 = __float_as_uint(Pl[arow * SPW + kc + 4]);
            unsigned al3 = __float_as_uint(Pl[(arow + 8) * SPW + kc + 4]);
#pragma unroll
            for (int nt = 0; nt < 4; nt++) {
                const int nb = nhpv + nt * 8 + (lane >> 2);
                const float v0 = Vr[(ks * 8 + kcl) * QSW + nb];
                const float v1 = Vr[(ks * 8 + kcl + 4) * QSW + nb];
                unsigned bh0 = tf32cvt(v0);
                unsigned bh1 = tf32cvt(v1);
                unsigned bl0 = tf32cvt(v0 - __uint_as_float(bh0));
                unsigned bl1 = tf32cvt(v1 - __uint_as_float(bh1));
                mma_tf32(accpv[nt][0], accpv[nt][1], accpv[nt][2], accpv[nt][3],
                         ah0, ah1, ah2, ah3, bh0, bh1);
                mma_tf32(accpv[nt][0], accpv[nt][1], accpv[nt][2], accpv[nt][3],
                         al0, al1, al2, al3, bh0, bh1);
                mma_tf32(accpv[nt][0], accpv[nt][1], accpv[nt][2], accpv[nt][3],
                         ah0, ah1, ah2, ah3, bl0, bl1);
            }
        }
        ts_reg = ts_next;
    }

    // ---- write out[b, l, h*64 + d] ----
    const int b_idx = bh / HH;
    const int h     = bh % HH;
#pragma unroll
    for (int half = 0; half < 2; half++) {
        const int row = arow + half * 8;
        const float inv = 1.f / sum_state[row];
        const int l = l0 + row;
#pragma unroll
        for (int nt = 0; nt < 4; nt++) {
            const int col = nhpv + nt * 8 + 2 * (lane & 3);
            float2 r;
            r.x = accpv[nt][2 * half + 0] * inv;
            r.y = accpv[nt][2 * half + 1] * inv;
            *(float2*)&out[((size_t)(b_idx * LL + l)) * HIDD + h * DD + col] = r;
        }
    }
}

// ============================================================================
// launch
// ============================================================================
extern "C" void kernel_launch(void* const* d_in, const int* in_sizes, int n_in,
                              void* d_out, int out_size)
{
    (void)in_sizes; (void)n_in; (void)out_size;
    const float* hidden = (const float*)d_in[0];
    const float* mask   = (const float*)d_in[1];
    const float* S      = (const float*)d_in[2];
    const float* Wq     = (const float*)d_in[3];
    const float* bq     = (const float*)d_in[4];
    const float* Wk     = (const float*)d_in[5];
    const float* bk     = (const float*)d_in[6];
    const float* Wv     = (const float*)d_in[7];
    const float* bv     = (const float*)d_in[8];
    float* out = (float*)d_out;

    static int smem_set = 0;
    if (!smem_set) {
        cudaFuncSetAttribute(fused_attn_kernel,
                             cudaFuncAttributeMaxDynamicSharedMemorySize,
                             SMEM_FLOATS * (int)sizeof(float));
        smem_set = 1;
    }

    dim3 g1(64, 12, 3);
    qkv_mma_kernel<<<g1, 256>>>(hidden, Wq, bq, Wk, bk, Wv, bv);

    dim3 g2(16, 1024);
    bias_mma_kernel<<<g2, 256>>>(S, mask, 0);   // q-side -> g_biasq (bf16, +mask)
    bias_mma_kernel<<<g2, 256>>>(S, mask, 1);   // k-side -> g_biaskT (bf16)

    dim3 g3(16, 48);
    fused_attn_kernel<<<g3, 256, SMEM_FLOATS * sizeof(float)>>>(out);
}